// round 16
// baseline (speedup 1.0000x reference)
#include <cuda_runtime.h>
#include <cuda_fp16.h>
#include <cstdint>
#include <math.h>

#define D_MODEL   256
#define N_HEADS   8
#define LEN_IN    5440
#define LEN_Q     5440
#define BATCH     4
#define M_TOTAL   (BATCH * LEN_Q)   // 21760 = 1360 * 16

// ---------------- scratch (static device globals; no allocation) -------------
__device__ float g_off  [(size_t)M_TOTAL * 256];
__device__ float g_attn [(size_t)M_TOTAL * 128];
// fp16 value (row-major, written by value GEMM, read by sampling)
__device__ __align__(16) __half g_valueH[(size_t)M_TOTAL * 256];
// fp16 fragment-native A operands: [M/16][16 k16][32 lanes][8 halfs]
__device__ __align__(16) __half g_qh [(size_t)M_TOTAL * 256];
__device__ __align__(16) __half g_ih [(size_t)M_TOTAL * 256];
__device__ __align__(16) __half g_midh[(size_t)M_TOTAL * 256];
// fp16 fragment-native weights: [N/8][16 k16][32 lanes][4 halfs]
__device__ __align__(16) __half g_wvH [256 * 256];
__device__ __align__(16) __half g_woH [256 * 256];
__device__ __align__(16) __half g_waH [128 * 256];
__device__ __align__(16) __half g_wouH[256 * 256];

// ---------------- PTX helpers ------------------------------------------------
__device__ __forceinline__ uint32_t h2u(__half2 h) {
    return *reinterpret_cast<uint32_t*>(&h);
}
__device__ __forceinline__ uint32_t smem_u32(const void* p) {
    uint32_t a;
    asm("{ .reg .u64 t; cvta.to.shared.u64 t, %1; cvt.u32.u64 %0, t; }" : "=r"(a) : "l"(p));
    return a;
}
__device__ __forceinline__ void cp_async16(uint32_t dst, const void* src) {
    asm volatile("cp.async.cg.shared.global [%0], [%1], 16;" :: "r"(dst), "l"(src));
}
#define CP_COMMIT() asm volatile("cp.async.commit_group;" ::: "memory")
#define CP_WAIT(n)  asm volatile("cp.async.wait_group %0;" :: "n"(n) : "memory")

__device__ __forceinline__ void mma_f16(float* c, const uint32_t* a, const uint32_t* b) {
    asm volatile("mma.sync.aligned.m16n8k16.row.col.f32.f16.f16.f32 "
        "{%0,%1,%2,%3}, {%4,%5,%6,%7}, {%8,%9}, {%0,%1,%2,%3};"
        : "+f"(c[0]), "+f"(c[1]), "+f"(c[2]), "+f"(c[3])
        : "r"(a[0]), "r"(a[1]), "r"(a[2]), "r"(a[3]), "r"(b[0]), "r"(b[1]));
}

// ------ weights: transpose + fp16 + fragment-native [N/8][k16][lane][4h] -----
__global__ void conv_w(const float* __restrict__ Wv, const float* __restrict__ Wo,
                       const float* __restrict__ Wa, const float* __restrict__ Wou,
                       __half* __restrict__ WvH, __half* __restrict__ WoH,
                       __half* __restrict__ WaH, __half* __restrict__ WouH) {
    const int m = blockIdx.y;
    const float* W; __half* Wh; int N;
    if      (m == 0) { W = Wv;  Wh = WvH;  N = 256; }
    else if (m == 1) { W = Wo;  Wh = WoH;  N = 256; }
    else if (m == 2) { W = Wa;  Wh = WaH;  N = 128; }
    else             { W = Wou; Wh = WouH; N = 256; }
    const int slice = blockIdx.x * 8 + (threadIdx.x >> 5);   // (n8, k16)
    if (slice >= (N / 8) * 16) return;
    const int n8 = slice >> 4, k16 = slice & 15;
    const int lane = threadIdx.x & 31, gid = lane >> 2, tg = lane & 3;
    const int n = n8 * 8 + gid;
    const int k = k16 * 16 + 2 * tg;
    const float w0 = W[(size_t)k * N + n];
    const float w1 = W[(size_t)(k + 1) * N + n];
    const float w2 = W[(size_t)(k + 8) * N + n];
    const float w3 = W[(size_t)(k + 9) * N + n];
    uint2 v;
    v.x = h2u(__floats2half2_rn(w0, w1));
    v.y = h2u(__floats2half2_rn(w2, w3));
    *(uint2*)(Wh + (size_t)slice * 128 + lane * 4) = v;
}

// ------ A matrices: fp32 -> fp16 fragment-native [M/16][k16][lane][8h] -------
__global__ void __launch_bounds__(512)
conv_a(const float* __restrict__ Q, const float* __restrict__ I,
       __half* __restrict__ Qh, __half* __restrict__ Ih) {
    const int blk = blockIdx.x;
    const float* src = blockIdx.y ? I : Q;
    __half* dst      = blockIdx.y ? Ih : Qh;
    const int t = threadIdx.x;
    const int s = t >> 5, lane = t & 31, gid = lane >> 2, tg = lane & 3;
    const size_t r0 = (size_t)(blk * 16 + gid) * 256;
    const size_t r1 = r0 + 8 * 256;
    const int k = s * 16 + 2 * tg;
    const float2 v0 = *(const float2*)(src + r0 + k);
    const float2 v1 = *(const float2*)(src + r1 + k);
    const float2 v2 = *(const float2*)(src + r0 + k + 8);
    const float2 v3 = *(const float2*)(src + r1 + k + 8);
    uint4 o;
    o.x = h2u(__floats2half2_rn(v0.x, v0.y));
    o.y = h2u(__floats2half2_rn(v1.x, v1.y));
    o.z = h2u(__floats2half2_rn(v2.x, v2.y));
    o.w = h2u(__floats2half2_rn(v3.x, v3.y));
    *(uint4*)(dst + ((size_t)(blk * 16 + s) * 32 + lane) * 8) = o;
}

// ---------------- fp16 tensor-core GEMM --------------------------------------
// CTA 128x128, BK=32 (2 k16), 8 warps (2m x 4n), warp 64x32 (16x m16n8k16).
// fused: y0,1 value -> fp16 C; y2,3 offsets -> fp32; y4 attn -> fp32.
#define STAGE_B 16384                 // 8KB A + 8KB B
#define SMEM_HB (2 * STAGE_B)

__global__ void __launch_bounds__(256, 2)
gemm_fp16(const __half* __restrict__ A0, const __half* __restrict__ A1,
          const __half* __restrict__ W0, const __half* __restrict__ W1,
          const __half* __restrict__ W2,
          const float* __restrict__ b0, const float* __restrict__ b1,
          const float* __restrict__ b2,
          __half* __restrict__ CH, float* __restrict__ C1, float* __restrict__ C2,
          float* __restrict__ CF, int fused) {
    extern __shared__ char smc[];
    const int tid  = threadIdx.x;
    const int wid  = tid >> 5;
    const int lane = tid & 31;
    const int gid  = lane >> 2;
    const int tg   = lane & 3;
    const int bm   = blockIdx.x * 128;

    const __half *A, *Wt; const float* bias; int NTOT = 256; int bn;
    float* Cf = nullptr; __half* Ch = nullptr;
    {
        const int y = blockIdx.y;
        if (fused) {
            if (y < 2)      { A = A0; Wt = W0; bias = b0; Ch = CH; bn = y * 128; }
            else if (y < 4) { A = A1; Wt = W1; bias = b1; Cf = C1; bn = (y - 2) * 128; }
            else            { A = A1; Wt = W2; bias = b2; Cf = C2; bn = 0; NTOT = 128; }
        } else              { A = A0; Wt = W0; bias = b0; Cf = CF; bn = y * 128; }
    }
    const int m_blk_base = bm >> 4;
    const int n_blk_base = bn >> 3;
    const uint32_t smb = smem_u32(smc);

    auto load_tile = [&](int buf, int c) {
        const uint32_t sA = smb + buf * STAGE_B;
        const uint32_t sB = sA + 8192;
#pragma unroll
        for (int i = 0; i < 2; ++i) {
            const int u = tid + i * 256;          // 0..511
            {   // A: 16 slices x 512B
                const int ml = u >> 6, sl = (u >> 5) & 1, wi = u & 31;
                cp_async16(sA + (uint32_t)(((ml * 2 + sl) * 32 + wi) * 16),
                    A + ((size_t)(m_blk_base + ml) * 16 + (2 * c + sl)) * 256 + wi * 8);
            }
            {   // B: 32 slices x 256B
                const int nl = u >> 5, sl = (u >> 4) & 1, wi = u & 15;
                cp_async16(sB + (uint32_t)(((nl * 2 + sl) * 16 + wi) * 16),
                    Wt + ((size_t)(n_blk_base + nl) * 16 + (2 * c + sl)) * 128 + wi * 8);
            }
        }
        CP_COMMIT();
    };

    float acc[4][4][4];
#pragma unroll
    for (int mt = 0; mt < 4; ++mt)
#pragma unroll
        for (int nt = 0; nt < 4; ++nt)
#pragma unroll
            for (int i = 0; i < 4; ++i) acc[mt][nt][i] = 0.0f;

    load_tile(0, 0);
#pragma unroll 1
    for (int c = 0; c < 8; ++c) {
        if (c < 7) { load_tile((c + 1) & 1, c + 1); CP_WAIT(1); }
        else       { CP_WAIT(0); }
        __syncthreads();

        const char* As = smc + (c & 1) * STAGE_B;
        const char* Bs = As + 8192;
#pragma unroll
        for (int s = 0; s < 2; ++s) {
            uint2 bf[4];
#pragma unroll
            for (int nt = 0; nt < 4; ++nt) {
                const int nl = (wid & 3) * 4 + nt;
                bf[nt] = *(const uint2*)(Bs + (((nl * 2 + s) * 32 + lane) * 8));
            }
            uint4 af[4];
#pragma unroll
            for (int mt = 0; mt < 4; ++mt) {
                const int ml = (wid >> 2) * 4 + mt;
                af[mt] = *(const uint4*)(As + (((ml * 2 + s) * 32 + lane) * 16));
            }
#pragma unroll
            for (int mt = 0; mt < 4; ++mt)
#pragma unroll
                for (int nt = 0; nt < 4; ++nt)
                    mma_f16(acc[mt][nt], (const uint32_t*)&af[mt], (const uint32_t*)&bf[nt]);
        }
        __syncthreads();
    }

    const int mbase = (wid >> 2) * 64;
    const int nbase = (wid & 3) * 32;
#pragma unroll
    for (int mt = 0; mt < 4; ++mt) {
        const int row0 = bm + mbase + mt * 16 + gid;
#pragma unroll
        for (int nt = 0; nt < 4; ++nt) {
            const int col = bn + nbase + nt * 8 + tg * 2;
            const float2 bv = *(const float2*)(bias + col);
            const float c0 = acc[mt][nt][0] + bv.x, c1 = acc[mt][nt][1] + bv.y;
            const float c2 = acc[mt][nt][2] + bv.x, c3 = acc[mt][nt][3] + bv.y;
            if (Ch) {
                *(uint32_t*)(Ch + (size_t)row0 * 256 + col)       = h2u(__floats2half2_rn(c0, c1));
                *(uint32_t*)(Ch + (size_t)(row0 + 8) * 256 + col) = h2u(__floats2half2_rn(c2, c3));
            } else {
                *(float2*)(Cf + (size_t)row0 * NTOT + col)       = make_float2(c0, c1);
                *(float2*)(Cf + (size_t)(row0 + 8) * NTOT + col) = make_float2(c2, c3);
            }
        }
    }
}

// ---------------- sampling: 4-corner warp split ------------------------------
// warp = head. Producers (lanes 0-15) write per-point per-corner {byte_off, w}.
// Gather: 4 groups of 8 lanes = 4 corners; lane loads 4 channels (uint2).
// Corner partials summed via shfl_xor(8), shfl_xor(16).
__global__ void __launch_bounds__(256)
msda_sample(const float* __restrict__ refp) {
    const int bq   = blockIdx.x;
    const int b    = bq / LEN_Q;
    const int tid  = threadIdx.x;
    const int h    = tid >> 5;
    const int lane = tid & 31;

    __shared__ uint2 s_pk[8][16][4];   // [head][point][corner] = {byte_off, w}

    const size_t rowo = (size_t)bq * 256;

    {
        const int ln = lane & 15;           // point id
        const int l  = ln >> 2;             // level

        float logit = g_attn[(size_t)bq * 128 + h * 16 + ln];
        float m = logit;
#pragma unroll
        for (int s = 8; s; s >>= 1) m = fmaxf(m, __shfl_xor_sync(0xffffffffu, m, s, 16));
        float e = __expf(logit - m);
        float ssum = e;
#pragma unroll
        for (int s = 8; s; s >>= 1) ssum += __shfl_xor_sync(0xffffffffu, ssum, s, 16);
        const float aw = e / ssum;

        const int S  = 64 >> l;
        const int st = (l == 0) ? 0 : (l == 1) ? 4096 : (l == 2) ? 5120 : 5376;
        const float fs = (float)S;

        const float rx = refp[(size_t)bq * 8 + l * 2 + 0];
        const float ry = refp[(size_t)bq * 8 + l * 2 + 1];
        const float ox = g_off[rowo + h * 32 + ln * 2 + 0];
        const float oy = g_off[rowo + h * 32 + ln * 2 + 1];

        const float x = fmaf(rx, fs, ox) - 0.5f;
        const float y = fmaf(ry, fs, oy) - 0.5f;
        const float x0f = floorf(x), y0f = floorf(y);
        const int ix0 = (int)x0f, iy0 = (int)y0f;
        const float wx = x - x0f, wy = y - y0f;

        const float fx0 = (unsigned)ix0       < (unsigned)S ? 1.0f : 0.0f;
        const float fx1 = (unsigned)(ix0 + 1) < (unsigned)S ? 1.0f : 0.0f;
        const float fy0 = (unsigned)iy0       < (unsigned)S ? 1.0f : 0.0f;
        const float fy1 = (unsigned)(iy0 + 1) < (unsigned)S ? 1.0f : 0.0f;

        const int cx0 = min(max(ix0, 0), S - 1);
        const int cx1 = min(max(ix0 + 1, 0), S - 1);
        const int cy0 = min(max(iy0, 0), S - 1);
        const int cy1 = min(max(iy0 + 1, 0), S - 1);

        if (lane < 16) {
            uint2 c0, c1, c2, c3;   // TL, BL, TR, BR: byte offsets (x512)
            c0.x = (uint32_t)((st + cy0 * S + cx0) * 512);
            c0.y = __float_as_uint(aw * (1.0f - wx) * (1.0f - wy) * fx0 * fy0);
            c1.x = (uint32_t)((st + cy1 * S + cx0) * 512);
            c1.y = __float_as_uint(aw * (1.0f - wx) * wy          * fx0 * fy1);
            c2.x = (uint32_t)((st + cy0 * S + cx1) * 512);
            c2.y = __float_as_uint(aw * wx * (1.0f - wy) * fx1 * fy0);
            c3.x = (uint32_t)((st + cy1 * S + cx1) * 512);
            c3.y = __float_as_uint(aw * wx * wy          * fx1 * fy1);
            s_pk[h][ln][0] = c0;
            s_pk[h][ln][1] = c1;
            s_pk[h][ln][2] = c2;
            s_pk[h][ln][3] = c3;
        }
    }
    __syncwarp();

    const int corner = lane >> 3;           // 0..3
    const int ch4    = (lane & 7) * 4;      // 4-channel base within head
    const char* vb = (const char*)g_valueH
                   + ((size_t)b * (LEN_IN * 256) + h * 32 + ch4) * 2;

    float a0 = 0.f, a1 = 0.f, a2 = 0.f, a3 = 0.f;
#pragma unroll
    for (int p = 0; p < 16; ++p) {
        const uint2 pk = s_pk[h][p][corner];
        const uint2 v  = *(const uint2*)(vb + pk.x);
        const float w  = __uint_as_float(pk.y);
        const float2 f0 = __half22float2(*(const __half2*)&v.x);
        const float2 f1 = __half22float2(*(const __half2*)&v.y);
        a0 = fmaf(w, f0.x, a0);
        a1 = fmaf(w, f0.y, a1);
        a2 = fmaf(w, f1.x, a2);
        a3 = fmaf(w, f1.y, a3);
    }
    // sum the 4 corner partials (channels identical across corner groups)
#pragma unroll
    for (int s = 8; s <= 16; s <<= 1) {
        a0 += __shfl_xor_sync(0xffffffffu, a0, s);
        a1 += __shfl_xor_sync(0xffffffffu, a1, s);
        a2 += __shfl_xor_sync(0xffffffffu, a2, s);
        a3 += __shfl_xor_sync(0xffffffffu, a3, s);
    }

    if (lane < 16) {   // lane L: pair cc = 16h + 2*(L&7) + (L>>3)
        const int cc = h * 16 + 2 * (lane & 7) + (lane >> 3);
        const float lo = (lane < 8) ? a0 : a2;
        const float hi = (lane < 8) ? a1 : a3;
        const int g  = bq & 15;
        const int fl = (g & 7) * 4 + (cc & 3);
        const int slot = (g >> 3) + ((cc >> 2) & 1) * 2;
        const size_t h2i = ((size_t)((bq >> 4) * 16 + (cc >> 3)) * 32 + fl) * 4 + slot;
        ((__half2*)g_midh)[h2i] = __floats2half2_rn(lo, hi);
    }
}

// ---------------- launch -----------------------------------------------------
extern "C" void kernel_launch(void* const* d_in, const int* in_sizes, int n_in,
                              void* d_out, int out_size) {
    const float* query   = (const float*)d_in[0];
    const float* refp    = (const float*)d_in[1];
    const float* in_flat = (const float*)d_in[2];
    const float* W_val  = (const float*)d_in[5];
    const float* b_val  = (const float*)d_in[6];
    const float* W_off  = (const float*)d_in[7];
    const float* b_off  = (const float*)d_in[8];
    const float* W_attn = (const float*)d_in[9];
    const float* b_attn = (const float*)d_in[10];
    const float* W_out  = (const float*)d_in[11];
    const float* b_out  = (const float*)d_in[12];
    float* out = (float*)d_out;

    float *po, *pa;
    __half *vh, *qh, *ih, *mh, *wvH, *woH, *waH, *wouH;
    cudaGetSymbolAddress((void**)&po,  g_off);
    cudaGetSymbolAddress((void**)&pa,  g_attn);
    cudaGetSymbolAddress((void**)&vh,  g_valueH);
    cudaGetSymbolAddress((void**)&qh,  g_qh);
    cudaGetSymbolAddress((void**)&ih,  g_ih);
    cudaGetSymbolAddress((void**)&mh,  g_midh);
    cudaGetSymbolAddress((void**)&wvH, g_wvH);
    cudaGetSymbolAddress((void**)&woH, g_woH);
    cudaGetSymbolAddress((void**)&waH, g_waH);
    cudaGetSymbolAddress((void**)&wouH, g_wouH);

    cudaFuncSetAttribute(gemm_fp16, cudaFuncAttributeMaxDynamicSharedMemorySize, SMEM_HB);

    conv_w<<<dim3(64, 4), 256>>>(W_val, W_off, W_attn, W_out, wvH, woH, waH, wouH);
    conv_a<<<dim3(M_TOTAL / 16, 2), 512>>>(query, in_flat, qh, ih);

    // fused front GEMMs: value (y=0,1 -> fp16), offsets (y=2,3), attn (y=4)
    gemm_fp16<<<dim3(M_TOTAL / 128, 5), 256, SMEM_HB>>>(
        ih, qh, wvH, woH, waH, b_val, b_off, b_attn, vh, po, pa, nullptr, 1);

    msda_sample<<<M_TOTAL, 256>>>(refp);

    // output projection (fp32 out)
    gemm_fp16<<<dim3(M_TOTAL / 128, 2), 256, SMEM_HB>>>(
        mh, nullptr, wouH, nullptr, nullptr, b_out, nullptr, nullptr,
        nullptr, nullptr, nullptr, out, 0);
}

// round 17
// speedup vs baseline: 1.0686x; 1.0686x over previous
#include <cuda_runtime.h>
#include <cuda_fp16.h>
#include <cstdint>
#include <math.h>

#define D_MODEL   256
#define N_HEADS   8
#define LEN_IN    5440
#define LEN_Q     5440
#define BATCH     4
#define M_TOTAL   (BATCH * LEN_Q)   // 21760 = 1360 * 16
#define VGUARD    64                // halfs of zero guard each side

// ---------------- scratch (static device globals; no allocation) -------------
__device__ float g_off  [(size_t)M_TOTAL * 256];
__device__ float g_attn [(size_t)M_TOTAL * 128];
// fp16 value, HEAD-MAJOR: [b][h][loc][32ch], with zero guards both sides
__device__ __align__(16) __half g_valueH[VGUARD + (size_t)M_TOTAL * 256 + VGUARD];
// fp16 fragment-native A operands: [M/16][16 k16][32 lanes][8 halfs]
__device__ __align__(16) __half g_qh [(size_t)M_TOTAL * 256];
__device__ __align__(16) __half g_ih [(size_t)M_TOTAL * 256];
__device__ __align__(16) __half g_midh[(size_t)M_TOTAL * 256];
// fp16 fragment-native weights: [N/8][16 k16][32 lanes][4 halfs]
__device__ __align__(16) __half g_wvH [256 * 256];
__device__ __align__(16) __half g_woH [256 * 256];
__device__ __align__(16) __half g_waH [128 * 256];
__device__ __align__(16) __half g_wouH[256 * 256];

// ---------------- PTX helpers ------------------------------------------------
__device__ __forceinline__ uint32_t h2u(__half2 h) {
    return *reinterpret_cast<uint32_t*>(&h);
}
__device__ __forceinline__ uint32_t smem_u32(const void* p) {
    uint32_t a;
    asm("{ .reg .u64 t; cvta.to.shared.u64 t, %1; cvt.u32.u64 %0, t; }" : "=r"(a) : "l"(p));
    return a;
}
__device__ __forceinline__ void cp_async16(uint32_t dst, const void* src) {
    asm volatile("cp.async.cg.shared.global [%0], [%1], 16;" :: "r"(dst), "l"(src));
}
#define CP_COMMIT() asm volatile("cp.async.commit_group;" ::: "memory")
#define CP_WAIT(n)  asm volatile("cp.async.wait_group %0;" :: "n"(n) : "memory")

__device__ __forceinline__ void mma_f16(float* c, const uint32_t* a, const uint32_t* b) {
    asm volatile("mma.sync.aligned.m16n8k16.row.col.f32.f16.f16.f32 "
        "{%0,%1,%2,%3}, {%4,%5,%6,%7}, {%8,%9}, {%0,%1,%2,%3};"
        : "+f"(c[0]), "+f"(c[1]), "+f"(c[2]), "+f"(c[3])
        : "r"(a[0]), "r"(a[1]), "r"(a[2]), "r"(a[3]), "r"(b[0]), "r"(b[1]));
}

// ------ weights: transpose + fp16 + fragment-native [N/8][k16][lane][4h] -----
__global__ void conv_w(const float* __restrict__ Wv, const float* __restrict__ Wo,
                       const float* __restrict__ Wa, const float* __restrict__ Wou,
                       __half* __restrict__ WvH, __half* __restrict__ WoH,
                       __half* __restrict__ WaH, __half* __restrict__ WouH) {
    const int m = blockIdx.y;
    const float* W; __half* Wh; int N;
    if      (m == 0) { W = Wv;  Wh = WvH;  N = 256; }
    else if (m == 1) { W = Wo;  Wh = WoH;  N = 256; }
    else if (m == 2) { W = Wa;  Wh = WaH;  N = 128; }
    else             { W = Wou; Wh = WouH; N = 256; }
    const int slice = blockIdx.x * 8 + (threadIdx.x >> 5);   // (n8, k16)
    if (slice >= (N / 8) * 16) return;
    const int n8 = slice >> 4, k16 = slice & 15;
    const int lane = threadIdx.x & 31, gid = lane >> 2, tg = lane & 3;
    const int n = n8 * 8 + gid;
    const int k = k16 * 16 + 2 * tg;
    const float w0 = W[(size_t)k * N + n];
    const float w1 = W[(size_t)(k + 1) * N + n];
    const float w2 = W[(size_t)(k + 8) * N + n];
    const float w3 = W[(size_t)(k + 9) * N + n];
    uint2 v;
    v.x = h2u(__floats2half2_rn(w0, w1));
    v.y = h2u(__floats2half2_rn(w2, w3));
    *(uint2*)(Wh + (size_t)slice * 128 + lane * 4) = v;
}

// ------ A matrices: fp32 -> fp16 fragment-native [M/16][k16][lane][8h] -------
__global__ void __launch_bounds__(512)
conv_a(const float* __restrict__ Q, const float* __restrict__ I,
       __half* __restrict__ Qh, __half* __restrict__ Ih) {
    const int blk = blockIdx.x;
    const float* src = blockIdx.y ? I : Q;
    __half* dst      = blockIdx.y ? Ih : Qh;
    const int t = threadIdx.x;
    const int s = t >> 5, lane = t & 31, gid = lane >> 2, tg = lane & 3;
    const size_t r0 = (size_t)(blk * 16 + gid) * 256;
    const size_t r1 = r0 + 8 * 256;
    const int k = s * 16 + 2 * tg;
    const float2 v0 = *(const float2*)(src + r0 + k);
    const float2 v1 = *(const float2*)(src + r1 + k);
    const float2 v2 = *(const float2*)(src + r0 + k + 8);
    const float2 v3 = *(const float2*)(src + r1 + k + 8);
    uint4 o;
    o.x = h2u(__floats2half2_rn(v0.x, v0.y));
    o.y = h2u(__floats2half2_rn(v1.x, v1.y));
    o.z = h2u(__floats2half2_rn(v2.x, v2.y));
    o.w = h2u(__floats2half2_rn(v3.x, v3.y));
    *(uint4*)(dst + ((size_t)(blk * 16 + s) * 32 + lane) * 8) = o;
}

// ---------------- fp16 tensor-core GEMM --------------------------------------
// CTA 128x128, BK=32 (2 k16), 8 warps (2m x 4n), warp 64x32 (16x m16n8k16).
// fused: y0,1 value -> fp16 head-major C; y2,3 offsets -> fp32; y4 attn -> fp32.
#define STAGE_B 16384                 // 8KB A + 8KB B
#define SMEM_HB (2 * STAGE_B)

__global__ void __launch_bounds__(256, 2)
gemm_fp16(const __half* __restrict__ A0, const __half* __restrict__ A1,
          const __half* __restrict__ W0, const __half* __restrict__ W1,
          const __half* __restrict__ W2,
          const float* __restrict__ b0, const float* __restrict__ b1,
          const float* __restrict__ b2,
          __half* __restrict__ CH, float* __restrict__ C1, float* __restrict__ C2,
          float* __restrict__ CF, int fused) {
    extern __shared__ char smc[];
    const int tid  = threadIdx.x;
    const int wid  = tid >> 5;
    const int lane = tid & 31;
    const int gid  = lane >> 2;
    const int tg   = lane & 3;
    const int bm   = blockIdx.x * 128;

    const __half *A, *Wt; const float* bias; int NTOT = 256; int bn;
    float* Cf = nullptr; __half* Ch = nullptr;
    {
        const int y = blockIdx.y;
        if (fused) {
            if (y < 2)      { A = A0; Wt = W0; bias = b0; Ch = CH; bn = y * 128; }
            else if (y < 4) { A = A1; Wt = W1; bias = b1; Cf = C1; bn = (y - 2) * 128; }
            else            { A = A1; Wt = W2; bias = b2; Cf = C2; bn = 0; NTOT = 128; }
        } else              { A = A0; Wt = W0; bias = b0; Cf = CF; bn = y * 128; }
    }
    const int m_blk_base = bm >> 4;
    const int n_blk_base = bn >> 3;
    const uint32_t smb = smem_u32(smc);

    auto load_tile = [&](int buf, int c) {
        const uint32_t sA = smb + buf * STAGE_B;
        const uint32_t sB = sA + 8192;
#pragma unroll
        for (int i = 0; i < 2; ++i) {
            const int u = tid + i * 256;          // 0..511
            {   // A: 16 slices x 512B
                const int ml = u >> 6, sl = (u >> 5) & 1, wi = u & 31;
                cp_async16(sA + (uint32_t)(((ml * 2 + sl) * 32 + wi) * 16),
                    A + ((size_t)(m_blk_base + ml) * 16 + (2 * c + sl)) * 256 + wi * 8);
            }
            {   // B: 32 slices x 256B
                const int nl = u >> 5, sl = (u >> 4) & 1, wi = u & 15;
                cp_async16(sB + (uint32_t)(((nl * 2 + sl) * 16 + wi) * 16),
                    Wt + ((size_t)(n_blk_base + nl) * 16 + (2 * c + sl)) * 128 + wi * 8);
            }
        }
        CP_COMMIT();
    };

    float acc[4][4][4];
#pragma unroll
    for (int mt = 0; mt < 4; ++mt)
#pragma unroll
        for (int nt = 0; nt < 4; ++nt)
#pragma unroll
            for (int i = 0; i < 4; ++i) acc[mt][nt][i] = 0.0f;

    load_tile(0, 0);
#pragma unroll 1
    for (int c = 0; c < 8; ++c) {
        if (c < 7) { load_tile((c + 1) & 1, c + 1); CP_WAIT(1); }
        else       { CP_WAIT(0); }
        __syncthreads();

        const char* As = smc + (c & 1) * STAGE_B;
        const char* Bs = As + 8192;
#pragma unroll
        for (int s = 0; s < 2; ++s) {
            uint2 bf[4];
#pragma unroll
            for (int nt = 0; nt < 4; ++nt) {
                const int nl = (wid & 3) * 4 + nt;
                bf[nt] = *(const uint2*)(Bs + (((nl * 2 + s) * 32 + lane) * 8));
            }
            uint4 af[4];
#pragma unroll
            for (int mt = 0; mt < 4; ++mt) {
                const int ml = (wid >> 2) * 4 + mt;
                af[mt] = *(const uint4*)(As + (((ml * 2 + s) * 32 + lane) * 16));
            }
#pragma unroll
            for (int mt = 0; mt < 4; ++mt)
#pragma unroll
                for (int nt = 0; nt < 4; ++nt)
                    mma_f16(acc[mt][nt], (const uint32_t*)&af[mt], (const uint32_t*)&bf[nt]);
        }
        __syncthreads();
    }

    const int mbase = (wid >> 2) * 64;
    const int nbase = (wid & 3) * 32;
#pragma unroll
    for (int mt = 0; mt < 4; ++mt) {
        const int row0 = bm + mbase + mt * 16 + gid;
#pragma unroll
        for (int nt = 0; nt < 4; ++nt) {
            const int col = bn + nbase + nt * 8 + tg * 2;
            const float2 bv = *(const float2*)(bias + col);
            const float c0 = acc[mt][nt][0] + bv.x, c1 = acc[mt][nt][1] + bv.y;
            const float c2 = acc[mt][nt][2] + bv.x, c3 = acc[mt][nt][3] + bv.y;
            if (Ch) {
                // head-major store: [b][h][loc][32ch]
                const int h = col >> 5, ch = col & 31;
                const int b0i = row0 / LEN_Q, loc0 = row0 - b0i * LEN_Q;
                const int r1 = row0 + 8;
                const int b1i = r1 / LEN_Q, loc1 = r1 - b1i * LEN_Q;
                *(uint32_t*)(Ch + ((size_t)(b0i * 8 + h) * LEN_Q + loc0) * 32 + ch)
                    = h2u(__floats2half2_rn(c0, c1));
                *(uint32_t*)(Ch + ((size_t)(b1i * 8 + h) * LEN_Q + loc1) * 32 + ch)
                    = h2u(__floats2half2_rn(c2, c3));
            } else {
                *(float2*)(Cf + (size_t)row0 * NTOT + col)       = make_float2(c0, c1);
                *(float2*)(Cf + (size_t)(row0 + 8) * NTOT + col) = make_float2(c2, c3);
            }
        }
    }
}

// ---------------- sampling: head-major value, paired-corner loads ------------
// warp = head. One LDG.32 covers TL|TR (contiguous 128B); one covers BL|BR.
__global__ void __launch_bounds__(256)
msda_sample(const float* __restrict__ refp) {
    const int bq   = blockIdx.x;
    const int b    = bq / LEN_Q;
    const int tid  = threadIdx.x;
    const int h    = tid >> 5;
    const int lane = tid & 31;

    __shared__ int4 s_pk[8][16][2];   // [head][pt][side]: {base_top, base_bot, w_t, w_b}

    const size_t rowo = (size_t)bq * 256;

    {
        const int ln = lane & 15;           // point id
        const int l  = ln >> 2;             // level

        float logit = g_attn[(size_t)bq * 128 + h * 16 + ln];
        float m = logit;
#pragma unroll
        for (int s = 8; s; s >>= 1) m = fmaxf(m, __shfl_xor_sync(0xffffffffu, m, s, 16));
        float e = __expf(logit - m);
        float ssum = e;
#pragma unroll
        for (int s = 8; s; s >>= 1) ssum += __shfl_xor_sync(0xffffffffu, ssum, s, 16);
        const float aw = e / ssum;

        const int S  = 64 >> l;
        const int st = (l == 0) ? 0 : (l == 1) ? 4096 : (l == 2) ? 5120 : 5376;
        const float fs = (float)S;

        const float rx = refp[(size_t)bq * 8 + l * 2 + 0];
        const float ry = refp[(size_t)bq * 8 + l * 2 + 1];
        const float ox = g_off[rowo + h * 32 + ln * 2 + 0];
        const float oy = g_off[rowo + h * 32 + ln * 2 + 1];

        const float x = fmaf(rx, fs, ox) - 0.5f;
        const float y = fmaf(ry, fs, oy) - 0.5f;
        const float x0f = floorf(x), y0f = floorf(y);
        const int ix0 = (int)x0f, iy0 = (int)y0f;
        const float wx = x - x0f, wy = y - y0f;

        const float fx0 = (unsigned)ix0       < (unsigned)S ? 1.0f : 0.0f;
        const float fx1 = (unsigned)(ix0 + 1) < (unsigned)S ? 1.0f : 0.0f;
        const float fy0 = (unsigned)iy0       < (unsigned)S ? 1.0f : 0.0f;
        const float fy1 = (unsigned)(iy0 + 1) < (unsigned)S ? 1.0f : 0.0f;

        // x base clamped to [-1, S-1]: paired 128B load stays within guards
        const int xb  = min(max(ix0, -1), S - 1);
        const int cy0 = min(max(iy0, 0), S - 1);
        const int cy1 = min(max(iy0 + 1, 0), S - 1);

        if (lane < 16) {
            const int bt = (st + cy0 * S + xb) * 64;   // bytes
            const int bb = (st + cy1 * S + xb) * 64;
            int4 s0, s1;
            s0.x = bt; s0.y = bb;
            s0.z = __float_as_uint(aw * (1.0f - wx) * (1.0f - wy) * fx0 * fy0);
            s0.w = __float_as_uint(aw * (1.0f - wx) * wy          * fx0 * fy1);
            s1.x = bt; s1.y = bb;
            s1.z = __float_as_uint(aw * wx * (1.0f - wy) * fx1 * fy0);
            s1.w = __float_as_uint(aw * wx * wy          * fx1 * fy1);
            s_pk[h][ln][0] = s0;
            s_pk[h][ln][1] = s1;
        }
    }
    __syncwarp();

    const int side = lane >> 4;             // 0: left col, 1: right col
    // lane's 4B slot within the 128B [left|right] pair block
    const char* vb = (const char*)(g_valueH + VGUARD)
                   + (size_t)(b * 8 + h) * (LEN_Q * 64) + lane * 4;

    float a0 = 0.f, a1 = 0.f, a2 = 0.f, a3 = 0.f;
#pragma unroll
    for (int p = 0; p < 16; ++p) {
        const int4 pk = s_pk[h][p][side];
        const uint32_t vt = *(const uint32_t*)(vb + pk.x);
        const uint32_t vo = *(const uint32_t*)(vb + pk.y);
        const float wt = __int_as_float(pk.z);
        const float wb = __int_as_float(pk.w);
        const float2 ft = __half22float2(*(const __half2*)&vt);
        const float2 fb = __half22float2(*(const __half2*)&vo);
        a0 = fmaf(wt, ft.x, a0);
        a1 = fmaf(wt, ft.y, a1);
        a2 = fmaf(wb, fb.x, a2);
        a3 = fmaf(wb, fb.y, a3);
    }
    float ox_ = a0 + a2;
    float oy_ = a1 + a3;
    ox_ += __shfl_xor_sync(0xffffffffu, ox_, 16);
    oy_ += __shfl_xor_sync(0xffffffffu, oy_, 16);

    if (lane < 16) {   // store fp16 at fragment-native position
        const int c  = h * 16 + (lane & 15);   // global k-pair index 0..127
        const int g  = bq & 15;
        const int fl = (g & 7) * 4 + (c & 3);            // lane within frag
        const int slot = (g >> 3) + ((c >> 2) & 1) * 2;  // half2 slot 0..3
        const size_t h2i = ((size_t)((bq >> 4) * 16 + (c >> 3)) * 32 + fl) * 4 + slot;
        ((__half2*)g_midh)[h2i] = __floats2half2_rn(ox_, oy_);
    }
}

// ---------------- launch -----------------------------------------------------
extern "C" void kernel_launch(void* const* d_in, const int* in_sizes, int n_in,
                              void* d_out, int out_size) {
    const float* query   = (const float*)d_in[0];
    const float* refp    = (const float*)d_in[1];
    const float* in_flat = (const float*)d_in[2];
    const float* W_val  = (const float*)d_in[5];
    const float* b_val  = (const float*)d_in[6];
    const float* W_off  = (const float*)d_in[7];
    const float* b_off  = (const float*)d_in[8];
    const float* W_attn = (const float*)d_in[9];
    const float* b_attn = (const float*)d_in[10];
    const float* W_out  = (const float*)d_in[11];
    const float* b_out  = (const float*)d_in[12];
    float* out = (float*)d_out;

    float *po, *pa;
    __half *vh, *qh, *ih, *mh, *wvH, *woH, *waH, *wouH;
    cudaGetSymbolAddress((void**)&po,  g_off);
    cudaGetSymbolAddress((void**)&pa,  g_attn);
    cudaGetSymbolAddress((void**)&vh,  g_valueH);
    cudaGetSymbolAddress((void**)&qh,  g_qh);
    cudaGetSymbolAddress((void**)&ih,  g_ih);
    cudaGetSymbolAddress((void**)&mh,  g_midh);
    cudaGetSymbolAddress((void**)&wvH, g_wvH);
    cudaGetSymbolAddress((void**)&woH, g_woH);
    cudaGetSymbolAddress((void**)&waH, g_waH);
    cudaGetSymbolAddress((void**)&wouH, g_wouH);

    cudaFuncSetAttribute(gemm_fp16, cudaFuncAttributeMaxDynamicSharedMemorySize, SMEM_HB);

    conv_w<<<dim3(64, 4), 256>>>(W_val, W_off, W_attn, W_out, wvH, woH, waH, wouH);
    conv_a<<<dim3(M_TOTAL / 16, 2), 512>>>(query, in_flat, qh, ih);

    // fused front GEMMs: value (y=0,1 -> fp16 head-major, +guard offset),
    // offsets (y=2,3), attn (y=4)
    gemm_fp16<<<dim3(M_TOTAL / 128, 5), 256, SMEM_HB>>>(
        ih, qh, wvH, woH, waH, b_val, b_off, b_attn, vh + VGUARD, po, pa, nullptr, 1);

    msda_sample<<<M_TOTAL, 256>>>(refp);

    // output projection (fp32 out)
    gemm_fp16<<<dim3(M_TOTAL / 128, 2), 256, SMEM_HB>>>(
        mh, nullptr, wouH, nullptr, nullptr, b_out, nullptr, nullptr,
        nullptr, nullptr, nullptr, out, 0);
}